// round 1
// baseline (speedup 1.0000x reference)
#include <cuda_runtime.h>
#include <cstdint>

#define N_TOK 4096
#define DDIM  1024

// Scratch (device globals: allowed; no runtime allocation)
__device__ float g_Q[(size_t)N_TOK * DDIM];
__device__ float g_K[(size_t)N_TOK * DDIM];
__device__ float g_V[(size_t)N_TOK * DDIM];
__device__ float g_P[(size_t)N_TOK * N_TOK];
__device__ float g_rsum[N_TOK];

#define BM 128
#define BN 128
#define BK 16
#define PADK 17              // BK + 1 padding to dodge bank conflicts
#define TILE_U (BM * PADK)   // u32 elements per tile

__device__ __forceinline__ uint32_t f2tf32(float x) {
    uint32_t u;
    asm volatile("cvt.rna.tf32.f32 %0, %1;" : "=r"(u) : "f"(x));
    return u;
}

__device__ __forceinline__ void mma_tf32(float d[4], const uint32_t a[4], const uint32_t b[2]) {
    asm volatile(
        "mma.sync.aligned.m16n8k8.row.col.f32.tf32.tf32.f32 "
        "{%0,%1,%2,%3}, {%4,%5,%6,%7}, {%8,%9}, {%0,%1,%2,%3};\n"
        : "+f"(d[0]), "+f"(d[1]), "+f"(d[2]), "+f"(d[3])
        : "r"(a[0]), "r"(a[1]), "r"(a[2]), "r"(a[3]),
          "r"(b[0]), "r"(b[1]));
}

// Global -> registers. A is [M x K] row-major (lda = K-stride).
// B_DIRECT: B stored [N x K] row-major (e.g. K-matrix for Q@K^T).
// !B_DIRECT: B stored [K x N] row-major (e.g. weights W, V) -> transposed into smem.
template <bool B_DIRECT>
__device__ __forceinline__ void global_load(
    const float* __restrict__ A, const float* __restrict__ B,
    int lda, int ldb, int bm, int bn, int kt, int tid,
    float4 ra[2], float4 rb[2])
{
#pragma unroll
    for (int i = 0; i < 2; i++) {
        int f = tid + i * 256;           // 512 float4 per tile
        int row = f >> 2, c4 = f & 3;    // 128 rows x 4 float4 (16 floats)
        ra[i] = *reinterpret_cast<const float4*>(
            A + (size_t)(bm + row) * lda + (size_t)kt * BK + c4 * 4);
        if (B_DIRECT) {
            rb[i] = *reinterpret_cast<const float4*>(
                B + (size_t)(bn + row) * ldb + (size_t)kt * BK + c4 * 4);
        } else {
            int krow = f >> 5, nc4 = f & 31;  // 16 k-rows x 32 float4 (128 n)
            rb[i] = *reinterpret_cast<const float4*>(
                B + (size_t)(kt * BK + krow) * ldb + bn + nc4 * 4);
        }
    }
}

// Registers -> smem (tf32-rounded). smem layout: sA[m][k], sB[n][k], stride PADK.
template <bool B_DIRECT>
__device__ __forceinline__ void smem_store(
    uint32_t* sA, uint32_t* sB, int tid, const float4 ra[2], const float4 rb[2])
{
#pragma unroll
    for (int i = 0; i < 2; i++) {
        int f = tid + i * 256;
        int row = f >> 2, c4 = f & 3;
        uint32_t* pa = sA + row * PADK + c4 * 4;
        pa[0] = f2tf32(ra[i].x); pa[1] = f2tf32(ra[i].y);
        pa[2] = f2tf32(ra[i].z); pa[3] = f2tf32(ra[i].w);
        if (B_DIRECT) {
            uint32_t* pb = sB + row * PADK + c4 * 4;
            pb[0] = f2tf32(rb[i].x); pb[1] = f2tf32(rb[i].y);
            pb[2] = f2tf32(rb[i].z); pb[3] = f2tf32(rb[i].w);
        } else {
            int krow = f >> 5, nc4 = f & 31;
            sB[(nc4 * 4 + 0) * PADK + krow] = f2tf32(rb[i].x);
            sB[(nc4 * 4 + 1) * PADK + krow] = f2tf32(rb[i].y);
            sB[(nc4 * 4 + 2) * PADK + krow] = f2tf32(rb[i].z);
            sB[(nc4 * 4 + 3) * PADK + krow] = f2tf32(rb[i].w);
        }
    }
}

// 128x128 CTA tile, 8 warps as 4(M) x 2(N), warp tile 32x64.
// Double-buffered smem mainloop; acc[mi(2)][ni(8)][4].
template <bool B_DIRECT>
__device__ __forceinline__ void gemm_main(
    const float* __restrict__ A, const float* __restrict__ B,
    int lda, int ldb, int kIters, int bm, int bn,
    uint32_t* smem, float (&acc)[2][8][4])
{
    uint32_t* sA = smem;
    uint32_t* sB = smem + 2 * TILE_U;
    const int tid = threadIdx.x;

#pragma unroll
    for (int mi = 0; mi < 2; mi++)
#pragma unroll
        for (int ni = 0; ni < 8; ni++)
#pragma unroll
            for (int j = 0; j < 4; j++) acc[mi][ni][j] = 0.f;

    float4 ra[2], rb[2];
    global_load<B_DIRECT>(A, B, lda, ldb, bm, bn, 0, tid, ra, rb);
    smem_store<B_DIRECT>(sA, sB, tid, ra, rb);
    __syncthreads();

    const int w = tid >> 5, lane = tid & 31;
    const int wm = (w & 3) * 32, wn = (w >> 2) * 64;
    const int gid = lane >> 2, tig = lane & 3;

    for (int kt = 0; kt < kIters; ++kt) {
        if (kt + 1 < kIters)
            global_load<B_DIRECT>(A, B, lda, ldb, bm, bn, kt + 1, tid, ra, rb);

        const uint32_t* cA = sA + (kt & 1) * TILE_U;
        const uint32_t* cB = sB + (kt & 1) * TILE_U;

#pragma unroll
        for (int ks = 0; ks < BK / 8; ks++) {
            const int k0 = ks * 8;
            uint32_t af[2][4], bf[8][2];
#pragma unroll
            for (int mi = 0; mi < 2; mi++) {
                int r = wm + mi * 16 + gid;
                af[mi][0] = cA[(r    ) * PADK + k0 + tig];
                af[mi][1] = cA[(r + 8) * PADK + k0 + tig];
                af[mi][2] = cA[(r    ) * PADK + k0 + tig + 4];
                af[mi][3] = cA[(r + 8) * PADK + k0 + tig + 4];
            }
#pragma unroll
            for (int ni = 0; ni < 8; ni++) {
                int c = wn + ni * 8 + gid;
                bf[ni][0] = cB[c * PADK + k0 + tig];
                bf[ni][1] = cB[c * PADK + k0 + tig + 4];
            }
#pragma unroll
            for (int mi = 0; mi < 2; mi++)
#pragma unroll
                for (int ni = 0; ni < 8; ni++)
                    mma_tf32(acc[mi][ni], af[mi], bf[ni]);
        }

        if (kt + 1 < kIters)
            smem_store<B_DIRECT>(sA + ((kt + 1) & 1) * TILE_U,
                                 sB + ((kt + 1) & 1) * TILE_U, tid, ra, rb);
        __syncthreads();
    }
}

// ---------- Kernel 1: Q/K/V = X @ W + b (blockIdx.z selects which) ----------
__global__ void __launch_bounds__(256)
qkv_kernel(const float* __restrict__ x,
           const float* __restrict__ Wq, const float* __restrict__ bq,
           const float* __restrict__ Wk, const float* __restrict__ bk,
           const float* __restrict__ Wv, const float* __restrict__ bv)
{
    __shared__ uint32_t smem[4 * TILE_U];
    const float* W; const float* bias; float* O;
    if (blockIdx.z == 0)      { W = Wq; bias = bq; O = g_Q; }
    else if (blockIdx.z == 1) { W = Wk; bias = bk; O = g_K; }
    else                      { W = Wv; bias = bv; O = g_V; }

    const int bm = blockIdx.y * BM, bn = blockIdx.x * BN;
    float acc[2][8][4];
    gemm_main<false>(x, W, DDIM, DDIM, DDIM / BK, bm, bn, smem, acc);

    const int w = threadIdx.x >> 5, lane = threadIdx.x & 31;
    const int wm = (w & 3) * 32, wn = (w >> 2) * 64;
    const int gid = lane >> 2, tig = lane & 3;
#pragma unroll
    for (int mi = 0; mi < 2; mi++) {
        int r0 = bm + wm + mi * 16 + gid;
#pragma unroll
        for (int ni = 0; ni < 8; ni++) {
            int c = bn + wn + ni * 8 + 2 * tig;
            float b0 = bias[c], b1 = bias[c + 1];
            float2 v0 = make_float2(acc[mi][ni][0] + b0, acc[mi][ni][1] + b1);
            float2 v1 = make_float2(acc[mi][ni][2] + b0, acc[mi][ni][3] + b1);
            *reinterpret_cast<float2*>(&O[(size_t)r0 * DDIM + c]) = v0;
            *reinterpret_cast<float2*>(&O[(size_t)(r0 + 8) * DDIM + c]) = v1;
        }
    }
}

// ---------- Kernel 2: P = exp(tanh(Q @ K^T) / 32) (unnormalized softmax) ----------
__global__ void __launch_bounds__(256)
score_kernel()
{
    __shared__ uint32_t smem[4 * TILE_U];
    const int bm = blockIdx.y * BM, bn = blockIdx.x * BN;
    float acc[2][8][4];
    gemm_main<true>(g_Q, g_K, DDIM, DDIM, DDIM / BK, bm, bn, smem, acc);

    const int w = threadIdx.x >> 5, lane = threadIdx.x & 31;
    const int wm = (w & 3) * 32, wn = (w >> 2) * 64;
    const int gid = lane >> 2, tig = lane & 3;
    const float sc = 0.03125f;  // 1/sqrt(1024)
#pragma unroll
    for (int mi = 0; mi < 2; mi++) {
        int r0 = bm + wm + mi * 16 + gid;
#pragma unroll
        for (int ni = 0; ni < 8; ni++) {
            int c = bn + wn + ni * 8 + 2 * tig;
            float2 v0 = make_float2(expf(tanhf(acc[mi][ni][0]) * sc),
                                    expf(tanhf(acc[mi][ni][1]) * sc));
            float2 v1 = make_float2(expf(tanhf(acc[mi][ni][2]) * sc),
                                    expf(tanhf(acc[mi][ni][3]) * sc));
            *reinterpret_cast<float2*>(&g_P[(size_t)r0 * N_TOK + c]) = v0;
            *reinterpret_cast<float2*>(&g_P[(size_t)(r0 + 8) * N_TOK + c]) = v1;
        }
    }
}

// ---------- Kernel 3: row sums of P ----------
__global__ void __launch_bounds__(256)
rowsum_kernel()
{
    const int row = blockIdx.x;
    const float4* p = reinterpret_cast<const float4*>(g_P + (size_t)row * N_TOK);
    float s = 0.f;
#pragma unroll
    for (int i = 0; i < 4; i++) {
        float4 v = p[threadIdx.x + i * 256];
        s += (v.x + v.y) + (v.z + v.w);
    }
#pragma unroll
    for (int o = 16; o > 0; o >>= 1) s += __shfl_xor_sync(0xffffffffu, s, o);
    __shared__ float red[8];
    if ((threadIdx.x & 31) == 0) red[threadIdx.x >> 5] = s;
    __syncthreads();
    if (threadIdx.x < 8) {
        float t = red[threadIdx.x];
#pragma unroll
        for (int o = 4; o > 0; o >>= 1) t += __shfl_xor_sync(0xffu, t, o);
        if (threadIdx.x == 0) g_rsum[row] = t;
    }
}

// ---------- Kernel 4: out = (P @ V) / rsum ----------
__global__ void __launch_bounds__(256)
pv_kernel(float* __restrict__ out)
{
    __shared__ uint32_t smem[4 * TILE_U];
    const int bm = blockIdx.y * BM, bn = blockIdx.x * BN;
    float acc[2][8][4];
    gemm_main<false>(g_P, g_V, N_TOK, DDIM, N_TOK / BK, bm, bn, smem, acc);

    const int w = threadIdx.x >> 5, lane = threadIdx.x & 31;
    const int wm = (w & 3) * 32, wn = (w >> 2) * 64;
    const int gid = lane >> 2, tig = lane & 3;
#pragma unroll
    for (int mi = 0; mi < 2; mi++) {
        int r0 = bm + wm + mi * 16 + gid;
        float inv0 = 1.0f / g_rsum[r0];
        float inv1 = 1.0f / g_rsum[r0 + 8];
#pragma unroll
        for (int ni = 0; ni < 8; ni++) {
            int c = bn + wn + ni * 8 + 2 * tig;
            float2 v0 = make_float2(acc[mi][ni][0] * inv0, acc[mi][ni][1] * inv0);
            float2 v1 = make_float2(acc[mi][ni][2] * inv1, acc[mi][ni][3] * inv1);
            *reinterpret_cast<float2*>(&out[(size_t)r0 * DDIM + c]) = v0;
            *reinterpret_cast<float2*>(&out[(size_t)(r0 + 8) * DDIM + c]) = v1;
        }
    }
}

extern "C" void kernel_launch(void* const* d_in, const int* in_sizes, int n_in,
                              void* d_out, int out_size)
{
    const float* x  = (const float*)d_in[0];
    const float* Wq = (const float*)d_in[1];
    const float* bq = (const float*)d_in[2];
    const float* Wk = (const float*)d_in[3];
    const float* bk = (const float*)d_in[4];
    const float* Wv = (const float*)d_in[5];
    const float* bv = (const float*)d_in[6];
    float* out = (float*)d_out;

    qkv_kernel  <<<dim3(DDIM / BN, N_TOK / BM, 3), 256>>>(x, Wq, bq, Wk, bk, Wv, bv);
    score_kernel<<<dim3(N_TOK / BN, N_TOK / BM),   256>>>();
    rowsum_kernel<<<N_TOK, 256>>>();
    pv_kernel   <<<dim3(DDIM / BN, N_TOK / BM),    256>>>(out);
}